// round 16
// baseline (speedup 1.0000x reference)
#include <cuda_runtime.h>
#include <cuda_fp16.h>
#include <cstdint>

// ===========================================================================
// SplineCouplingLayer — fused HMMA 2-pass asymmetric split, 3 CTAs/SM (r16)
//  activations fp16 hi+lo (22 bit), weights fp16; pass1 ah*b (f32 acc),
//  pass2 al*b (f16 acc). Bias from global; layer-3 in two sequential halves.
// ===========================================================================

#define B_ROWS  131072
#define DIM     64
#define D_IN    32
#define TAILB   3.0f
#define TM      16
#define THREADS 256

#define XT_S   33
#define XA_S   40
#define H_S    520
#define STH_S  388            // stash half stride (384 + 4)

// smem byte offsets
#define SM_XT    0            // 16*33*4  = 2112
#define SM_XAH   2112         // 16*40*2  = 1280
#define SM_XAL   3392         // 1280
#define SM_H1H   4672         // 16*520*2 = 16640
#define SM_H1L   21312
#define SM_H2H   37952
#define SM_H2L   54592        // ends 71232
#define SM_ST0   4672         // 16*388*4 = 24832 (overlays H1, ends 29504)
#define SM_ST1   37952        // 24832 (overlays H2, ends 62784)
#define SM_TOTAL 71232

typedef unsigned int u32;

// W fragments (fp16): per (kc, nf): 32 lanes x uint2 {b0, b1}
__device__ uint2 g_F1[2 * 64 * 32];
__device__ uint2 g_F2[32 * 64 * 32];
__device__ uint2 g_F3[32 * 96 * 32];

__device__ __forceinline__ u32 smem_u32(const void* p) {
    u32 a;
    asm("{ .reg .u64 t; cvta.to.shared.u64 t, %1; cvt.u32.u64 %0, t; }"
        : "=r"(a) : "l"(p));
    return a;
}

#define LDSM_X4(r0, r1, r2, r3, a) \
    asm volatile("ldmatrix.sync.aligned.m8n8.x4.shared.b16 {%0,%1,%2,%3}, [%4];" \
                 : "=r"(r0), "=r"(r1), "=r"(r2), "=r"(r3) : "r"(a))

__device__ __forceinline__ void mma_f32(float* c, const u32* a, u32 b0, u32 b1) {
    asm volatile(
        "mma.sync.aligned.m16n8k16.row.col.f32.f16.f16.f32 "
        "{%0,%1,%2,%3},{%4,%5,%6,%7},{%8,%9},{%0,%1,%2,%3};"
        : "+f"(c[0]), "+f"(c[1]), "+f"(c[2]), "+f"(c[3])
        : "r"(a[0]), "r"(a[1]), "r"(a[2]), "r"(a[3]), "r"(b0), "r"(b1));
}
__device__ __forceinline__ void mma_f16(u32* c, const u32* a, u32 b0, u32 b1) {
    asm volatile(
        "mma.sync.aligned.m16n8k16.row.col.f16.f16.f16.f16 "
        "{%0,%1},{%2,%3,%4,%5},{%6,%7},{%0,%1};"
        : "+r"(c[0]), "+r"(c[1])
        : "r"(a[0]), "r"(a[1]), "r"(a[2]), "r"(a[3]), "r"(b0), "r"(b1));
}

__device__ __forceinline__ u32 pk2h(__half a, __half b) {
    return (u32)__half_as_ushort(a) | ((u32)__half_as_ushort(b) << 16);
}
__device__ __forceinline__ void split2h(float x, float y, u32 &hi, u32 &lo) {
    __half xh = __float2half_rn(x);
    __half yh = __float2half_rn(y);
    __half xl = __float2half_rn(x - __half2float(xh));
    __half yl = __float2half_rn(y - __half2float(yh));
    hi = pk2h(xh, yh);
    lo = pk2h(xl, yl);
}
__device__ __forceinline__ float lo_half(u32 v, int which) {
    __half h = __ushort_as_half((unsigned short)(which ? (v >> 16) : (v & 0xffff)));
    return __half2float(h);
}

__device__ __forceinline__ void load_afrag(
    u32 smb, int aoff_h, int aoff_l, int AS, int lane, int cK,
    u32 ah[4], u32 al[4])
{
    int r  = (lane & 7) + ((lane >> 3) & 1) * 8;
    int cc = cK + (lane >> 4) * 8;
    u32 off = (u32)(r * AS + cc) * 2;
    LDSM_X4(ah[0], ah[1], ah[2], ah[3], smb + aoff_h + off);
    LDSM_X4(al[0], al[1], al[2], al[3], smb + aoff_l + off);
}

// ---------------------------------------------------------------------------
// Layers 1/2: NT=8 n-tiles per warp (8 warps cover N=512)
// ---------------------------------------------------------------------------
template<int NT, int NCH, int NFN, bool RELU>
__device__ __forceinline__ void do_layer_lin(
    char* sm, u32 smb, int tid, const uint2* __restrict__ Fq,
    const float* __restrict__ biasg,
    int aoff_h, int aoff_l, int AS, int hoff_h, int hoff_l)
{
    const int wid = tid >> 5, lane = tid & 31;
    const int nf0 = wid * NT;

    float accF[NT][4];
    u32   accL[NT][2];
#pragma unroll
    for (int nt = 0; nt < NT; ++nt) {
#pragma unroll
        for (int q = 0; q < 4; ++q) accF[nt][q] = 0.f;
        accL[nt][0] = 0u; accL[nt][1] = 0u;
    }

#pragma unroll
    for (int c = 0; c < NCH; ++c) {
        u32 ah[4], al[4];
        load_afrag(smb, aoff_h, aoff_l, AS, lane, c * 16, ah, al);
#pragma unroll
        for (int g2 = 0; g2 < NT / 4; ++g2) {
            uint2 b[4];
#pragma unroll
            for (int i = 0; i < 4; ++i)
                b[i] = Fq[(c * NFN + nf0 + g2 * 4 + i) * 32 + lane];
#pragma unroll
            for (int i = 0; i < 4; ++i) {
                int nt = g2 * 4 + i;
                mma_f32(accF[nt], ah, b[i].x, b[i].y);
                mma_f16(accL[nt], al, b[i].x, b[i].y);
            }
        }
    }

    const int g  = lane >> 2;
    const int t2 = (lane & 3) * 2;
#pragma unroll
    for (int nt = 0; nt < NT; ++nt) {
        int col = nf0 * 8 + nt * 8 + t2;
        float b0v = __ldg(biasg + col), b1v = __ldg(biasg + col + 1);
        float v0 = accF[nt][0] + lo_half(accL[nt][0], 0) + b0v;
        float v1 = accF[nt][1] + lo_half(accL[nt][0], 1) + b1v;
        float v2 = accF[nt][2] + lo_half(accL[nt][1], 0) + b0v;
        float v3 = accF[nt][3] + lo_half(accL[nt][1], 1) + b1v;
        if (RELU) {
            v0 = fmaxf(v0, 0.f); v1 = fmaxf(v1, 0.f);
            v2 = fmaxf(v2, 0.f); v3 = fmaxf(v3, 0.f);
        }
        u32 h01, l01, h23, l23;
        split2h(v0, v1, h01, l01);
        split2h(v2, v3, h23, l23);
        u32 oA = (u32)(g * H_S + col) * 2;
        u32 oB = (u32)((g + 8) * H_S + col) * 2;
        *(u32*)(sm + hoff_h + oA) = h01;
        *(u32*)(sm + hoff_l + oA) = l01;
        *(u32*)(sm + hoff_h + oB) = h23;
        *(u32*)(sm + hoff_l + oB) = l23;
    }
}

// ---------------------------------------------------------------------------
// Layer 3 one half: NT=6 n-tiles per warp over 384 cols (hh selects half)
//  SYNC=true inserts the barrier between mainloop (H2 reads) and the stash
//  write that overlays H2.
// ---------------------------------------------------------------------------
template<bool SYNC>
__device__ __forceinline__ void do_layer3_half(
    char* sm, u32 smb, int tid, const uint2* __restrict__ Fq,
    const float* __restrict__ b3, int hh, int stash_off)
{
    const int wid = tid >> 5, lane = tid & 31;
    const int nf0 = hh * 48 + wid * 6;

    float accF[6][4];
    u32   accL[6][2];
#pragma unroll
    for (int nt = 0; nt < 6; ++nt) {
#pragma unroll
        for (int q = 0; q < 4; ++q) accF[nt][q] = 0.f;
        accL[nt][0] = 0u; accL[nt][1] = 0u;
    }

#pragma unroll
    for (int c = 0; c < 32; ++c) {
        u32 ah[4], al[4];
        load_afrag(smb, SM_H2H, SM_H2L, H_S, lane, c * 16, ah, al);
#pragma unroll
        for (int g2 = 0; g2 < 2; ++g2) {
            uint2 b[3];
#pragma unroll
            for (int i = 0; i < 3; ++i)
                b[i] = Fq[(c * 96 + nf0 + g2 * 3 + i) * 32 + lane];
#pragma unroll
            for (int i = 0; i < 3; ++i) {
                int nt = g2 * 3 + i;
                mma_f32(accF[nt], ah, b[i].x, b[i].y);
                mma_f16(accL[nt], al, b[i].x, b[i].y);
            }
        }
    }

    if (SYNC) __syncthreads();   // all warps done reading H2 before stash1 writes

    const int g  = lane >> 2;
    const int t2 = (lane & 3) * 2;
#pragma unroll
    for (int nt = 0; nt < 6; ++nt) {
        int lcol = wid * 48 + nt * 8 + t2;          // 0..383 within half
        int gcol = hh * 384 + lcol;
        float b0v = (gcol < 736)     ? __ldg(b3 + gcol)     : 0.f;
        float b1v = (gcol + 1 < 736) ? __ldg(b3 + gcol + 1) : 0.f;
        float v0 = accF[nt][0] + lo_half(accL[nt][0], 0) + b0v;
        float v1 = accF[nt][1] + lo_half(accL[nt][0], 1) + b1v;
        float v2 = accF[nt][2] + lo_half(accL[nt][1], 0) + b0v;
        float v3 = accF[nt][3] + lo_half(accL[nt][1], 1) + b1v;
        *(float2*)(sm + stash_off + ((u32)g * STH_S + lcol) * 4)
            = make_float2(v0, v1);
        *(float2*)(sm + stash_off + ((u32)(g + 8) * STH_S + lcol) * 4)
            = make_float2(v2, v3);
    }
}

// ---------------------------------------------------------------------------
__device__ __forceinline__ float softplusf(float z) {
    return (z > 20.f) ? z : __logf(1.f + __expf(z));
}
__device__ __forceinline__ void spline_eval(const float raw[23], float xv,
                                            float &y_out, float &ld_out)
{
    float w[8], h[8];
    float mw = raw[0], mh = raw[8];
#pragma unroll
    for (int i = 1; i < 8; ++i) { mw = fmaxf(mw, raw[i]); mh = fmaxf(mh, raw[8 + i]); }
    float sw = 0.f, sh = 0.f;
#pragma unroll
    for (int i = 0; i < 8; ++i) {
        w[i] = __expf(raw[i] - mw); sw += w[i];
        h[i] = __expf(raw[8 + i] - mh); sh += h[i];
    }
    float iw = 6.f / sw, ih = 6.f / sh;
#pragma unroll
    for (int i = 0; i < 8; ++i) { w[i] *= iw; h[i] *= ih; }
    float der[9]; der[0] = 1.f; der[8] = 1.f;
#pragma unroll
    for (int i = 0; i < 7; ++i) der[i + 1] = softplusf(raw[16 + i]);
    float cw[9], ch[9]; cw[0] = -TAILB; ch[0] = -TAILB;
#pragma unroll
    for (int i = 0; i < 8; ++i) { cw[i + 1] = cw[i] + w[i]; ch[i + 1] = ch[i] + h[i]; }
    bool inside = (xv >= -TAILB) && (xv <= TAILB);
    float xc = fminf(fmaxf(xv, -TAILB + 1e-6f), TAILB - 1e-6f);
    int idx = 0;
#pragma unroll
    for (int i = 1; i <= 8; ++i) idx += (cw[i] < xc) ? 1 : 0;
    idx = min(idx, 7);
    float wk = w[0], hk = h[0], dk = der[0], dk1 = der[1], cwk = cw[0], chk = ch[0];
#pragma unroll
    for (int i = 1; i < 8; ++i) {
        bool sel = (idx == i);
        wk = sel ? w[i] : wk;   hk = sel ? h[i] : hk;
        dk = sel ? der[i] : dk; dk1 = sel ? der[i + 1] : dk1;
        cwk = sel ? cw[i] : cwk; chk = sel ? ch[i] : chk;
    }
    float xi = fminf(fmaxf((xc - cwk) / wk, 1e-6f), 1.f - 1e-6f);
    float om = 1.f - xi;
    float s = hk / wk;
    float num = hk * (s * xi * xi + dk * xi * om);
    float den = s + (dk + dk1 - 2.f * s) * xi * om;
    float yin = chk + num / den;
    float nld = s * s * (dk1 * xi * xi + 2.f * s * xi * om + dk * om * om);
    float ldin = __logf(nld + 1e-8f) - __logf(den * den + 1e-8f);
    y_out = inside ? yin : xv;
    ld_out = inside ? ldin : 0.f;
}

// ---------------------------------------------------------------------------
__global__ void __launch_bounds__(THREADS, 3)
spline_fused(const float* __restrict__ x,
             const float* __restrict__ b1, const float* __restrict__ b2,
             const float* __restrict__ b3, float* __restrict__ out)
{
    extern __shared__ char sm[];
    const u32 smb = smem_u32(sm);
    const int tid  = threadIdx.x;
    const int wid  = tid >> 5, lane = tid & 31;
    const int row0 = blockIdx.x * TM;

    // x tile: masked -> XA hi/lo + passthrough; transform -> XT
#pragma unroll
    for (int it = 0; it < 4; ++it) {
        int idx = tid + it * THREADS;
        int r = idx >> 6, c = idx & 63;
        float v = x[(size_t)(row0 + r) * DIM + c];
        if (c < D_IN) {
            out[(size_t)(row0 + r) * DIM + c] = v;
            __half hh = __float2half_rn(v);
            __half ll = __float2half_rn(v - __half2float(hh));
            *(__half*)(sm + SM_XAH + (u32)(r * XA_S + c) * 2) = hh;
            *(__half*)(sm + SM_XAL + (u32)(r * XA_S + c) * 2) = ll;
        } else {
            *(float*)(sm + SM_XT + (u32)(r * XT_S + (c - D_IN)) * 4) = v;
        }
    }
    __syncthreads();

    do_layer_lin<8, 2, 64, true>(sm, smb, tid, g_F1, b1,
                                 SM_XAH, SM_XAL, XA_S, SM_H1H, SM_H1L);
    __syncthreads();
    do_layer_lin<8, 32, 64, true>(sm, smb, tid, g_F2, b2,
                                  SM_H1H, SM_H1L, H_S, SM_H2H, SM_H2L);
    __syncthreads();

    // layer 3: half 0 stash overlays dead H1 (no extra sync needed);
    // half 1 stash overlays H2 (barrier inside, before the writes)
    do_layer3_half<false>(sm, smb, tid, g_F3, b3, 0, SM_ST0);
    do_layer3_half<true >(sm, smb, tid, g_F3, b3, 1, SM_ST1);
    __syncthreads();

    // spline: warp w -> rows {w, w+8}
    const float* st0 = (const float*)(sm + SM_ST0);
    const float* st1 = (const float*)(sm + SM_ST1);
    const float* xtf = (const float*)(sm + SM_XT);
#pragma unroll
    for (int it = 0; it < 2; ++it) {
        int row = wid + it * 8, d = lane;
        float raw[23];
        int base = d * 23;
#pragma unroll
        for (int j = 0; j < 23; ++j) {
            int col = base + j;
            raw[j] = (col < 384) ? st0[(u32)row * STH_S + col]
                                 : st1[(u32)row * STH_S + col - 384];
        }
        float xv = xtf[row * XT_S + d];
        float yv, ld;
        spline_eval(raw, xv, yv, ld);
        int gr = row0 + row;
        out[(size_t)gr * DIM + D_IN + d] = yv;
#pragma unroll
        for (int off = 16; off; off >>= 1)
            ld += __shfl_xor_sync(0xffffffffu, ld, off);
        if (d == 0) out[(size_t)B_ROWS * DIM + gr] = ld;
    }
}

// ---------------------------------------------------------------------------
// prep: pack W (rounded to fp16) into fragment-order uint2 {b0, b1}
// ---------------------------------------------------------------------------
__device__ __forceinline__ void frag_pack(
    const float* __restrict__ W, int N, int nvalid, int k0, int n, int t,
    uint2* __restrict__ F, u32 base)
{
    float w00 = 0.f, w01 = 0.f, w10 = 0.f, w11 = 0.f;
    if (n < nvalid) {
        w00 = W[(size_t)(k0 + 2 * t)     * N + n];
        w01 = W[(size_t)(k0 + 2 * t + 1) * N + n];
        w10 = W[(size_t)(k0 + 2 * t + 8) * N + n];
        w11 = W[(size_t)(k0 + 2 * t + 9) * N + n];
    }
    u32 b0 = pk2h(__float2half_rn(w00), __float2half_rn(w01));
    u32 b1 = pk2h(__float2half_rn(w10), __float2half_rn(w11));
    F[base] = make_uint2(b0, b1);
}

__global__ void __launch_bounds__(256)
prep_kernel(const float* __restrict__ W1, const float* __restrict__ W2,
            const float* __restrict__ W3)
{
    const int T1 = 2 * 64 * 32;
    const int T2 = 32 * 64 * 32;
    const int T3 = 32 * 96 * 32;
    for (int id = blockIdx.x * 256 + threadIdx.x; id < T1 + T2 + T3;
         id += gridDim.x * 256) {
        if (id < T1) {
            int lane = id & 31, fid = id >> 5;
            int nf = fid % 64, kc = fid / 64;
            frag_pack(W1, 512, 512, kc * 16, nf * 8 + (lane >> 2), lane & 3,
                      g_F1, (u32)(fid * 32 + lane));
        } else if (id < T1 + T2) {
            int i = id - T1;
            int lane = i & 31, fid = i >> 5;
            int nf = fid % 64, kc = fid / 64;
            frag_pack(W2, 512, 512, kc * 16, nf * 8 + (lane >> 2), lane & 3,
                      g_F2, (u32)(fid * 32 + lane));
        } else {
            int i = id - T1 - T2;
            int lane = i & 31, fid = i >> 5;
            int nf = fid % 96, kc = fid / 96;
            frag_pack(W3, 736, 736, kc * 16, nf * 8 + (lane >> 2), lane & 3,
                      g_F3, (u32)(fid * 32 + lane));
        }
    }
}

// ---------------------------------------------------------------------------
extern "C" void kernel_launch(void* const* d_in, const int* in_sizes, int n_in,
                              void* d_out, int out_size)
{
    (void)in_sizes; (void)n_in; (void)out_size;
    const float* x  = (const float*)d_in[0];
    const float* W1 = (const float*)d_in[1];
    const float* b1 = (const float*)d_in[2];
    const float* W2 = (const float*)d_in[3];
    const float* b2 = (const float*)d_in[4];
    const float* W3 = (const float*)d_in[5];
    const float* b3 = (const float*)d_in[6];
    float* out = (float*)d_out;

    prep_kernel<<<656, 256>>>(W1, W2, W3);

    cudaFuncSetAttribute(spline_fused,
                         cudaFuncAttributeMaxDynamicSharedMemorySize, SM_TOTAL);
    spline_fused<<<B_ROWS / TM, THREADS, SM_TOTAL>>>(x, b1, b2, b3, out);
}